// round 4
// baseline (speedup 1.0000x reference)
#include <cuda_runtime.h>
#include <cstdint>

// ---------------- problem constants ----------------
constexpr int Tn   = 128;   // seq len
constexpr int Bq   = 256;   // batch
constexpr int Hh   = 512;   // hidden
constexpr int Ee   = 16;    // embed
constexpr int Ln   = 4;     // layers
constexpr int G4   = 2048;  // 4H

// ---------------- device scratch (static; no allocation) ----------------
__device__ float d_Wih0[2 * G4 * Ee];           // tf32-rounded copies
__device__ float d_Whh0[2 * G4 * Hh];
__device__ float d_WihL[3 * 2 * G4 * 1024];
__device__ float d_WhhL[3 * 2 * G4 * Hh];
__device__ float d_bias[Ln * 2 * G4];           // bih + bhh
__device__ float d_x0[Tn * Bq * Ee];            // rounded embed[tokens]
__device__ float d_h[3][Ln * 2 * Bq * Hh];      // 3-deep ring of h state (wavefront-safe)
__device__ float d_c[Ln * 2 * Bq * Hh];         // c state (in-place)

// ---------------- helpers ----------------
__device__ __forceinline__ float tf32r(float x) {
    uint32_t u;
    asm("cvt.rna.tf32.f32 %0, %1;" : "=r"(u) : "f"(x));
    return __uint_as_float(u);
}

__device__ __forceinline__ void cp16(float* dst, const float* src) {
    unsigned s = (unsigned)__cvta_generic_to_shared(dst);
    asm volatile("cp.async.cg.shared.global [%0], [%1], 16;\n" :: "r"(s), "l"(src));
}
__device__ __forceinline__ void cp_commit() { asm volatile("cp.async.commit_group;\n"); }
template <int N>
__device__ __forceinline__ void cp_wait() { asm volatile("cp.async.wait_group %0;\n" :: "n"(N)); }

__device__ __forceinline__ void mma_tf32(float* c,
                                         uint32_t a0, uint32_t a1, uint32_t a2, uint32_t a3,
                                         uint32_t b0, uint32_t b1) {
    asm volatile(
        "mma.sync.aligned.m16n8k8.row.col.f32.tf32.tf32.f32 "
        "{%0,%1,%2,%3},{%4,%5,%6,%7},{%8,%9},{%0,%1,%2,%3};\n"
        : "+f"(c[0]), "+f"(c[1]), "+f"(c[2]), "+f"(c[3])
        : "r"(a0), "r"(a1), "r"(a2), "r"(a3), "r"(b0), "r"(b1));
}

__device__ __forceinline__ float sigf(float x) { return 1.0f / (1.0f + __expf(-x)); }

// ---------------- init ----------------
__global__ void init_kernel(const int* __restrict__ tokens, const float* __restrict__ embed,
                            const float* __restrict__ Wih0, const float* __restrict__ Whh0,
                            const float* __restrict__ bih0, const float* __restrict__ bhh0,
                            const float* __restrict__ Wih,  const float* __restrict__ Whh,
                            const float* __restrict__ bih,  const float* __restrict__ bhh) {
    const int idx0   = blockIdx.x * blockDim.x + threadIdx.x;
    const int stride = gridDim.x * blockDim.x;

    for (int i = idx0; i < 2 * G4 * Ee; i += stride)       d_Wih0[i] = tf32r(Wih0[i]);
    for (int i = idx0; i < 2 * G4 * Hh; i += stride)       d_Whh0[i] = tf32r(Whh0[i]);
    for (int i = idx0; i < 3 * 2 * G4 * 1024; i += stride) d_WihL[i] = tf32r(Wih[i]);
    for (int i = idx0; i < 3 * 2 * G4 * Hh; i += stride)   d_WhhL[i] = tf32r(Whh[i]);

    for (int i = idx0; i < Ln * 2 * G4; i += stride) {
        int l = i / (2 * G4), r = i % (2 * G4);
        d_bias[i] = (l == 0) ? (bih0[r] + bhh0[r])
                             : (bih[(l - 1) * 2 * G4 + r] + bhh[(l - 1) * 2 * G4 + r]);
    }
    for (int i = idx0; i < Tn * Bq * Ee; i += stride) {
        int t = i / (Bq * Ee);
        int rem = i % (Bq * Ee);
        int b = rem / Ee, e = rem % Ee;
        d_x0[i] = tf32r(embed[tokens[t * Bq + b] * Ee + e]);
    }
    for (int i = idx0; i < Ln * 2 * Bq * Hh; i += stride) {
        d_h[0][i] = 0.f;
        d_h[1][i] = 0.f;
        d_h[2][i] = 0.f;   // t=0 reads hprev from ring slot 2 -> must be zero
        d_c[i]    = 0.f;
    }
}

// ---------------- one LSTM cell (t, l, dir): 128 batch x 32 hidden units per block ----------------
// Block tile: C[128, 128] (128 batch rows x 32 units x 4 gates).
// 8 warps in a 4x2 grid of 32x64 warp tiles; acc[2][8][4].
// Ring-buffer contract: cell (t,l) writes h into d_h[t%3]; reads hprev from d_h[(t+2)%3];
// reads x (l>0) from d_h[t%3] slot l-1 (written by (t,l-1) in an earlier wavefront).
template <int KIN>
__device__ __forceinline__ void lstm_cell(int t, int l, int dir, float* smem) {
    constexpr int NIT = (KIN + Hh) / 16;
    float* sA = smem;          // [2][128][20] = 5120 floats
    float* sB = smem + 5120;   // [2][128][20] = 5120 floats

    const int tid = threadIdx.x;
    const int mt  = blockIdx.x;   // 0..1
    const int jt  = blockIdx.y;   // 0..15
    const int b0  = mt * 128, j0 = jt * 32;

    const int rb = (t + 2) % 3, wb = t % 3;
    const float* __restrict__ hprevD = d_h[rb] + (l * 2 + dir) * Bq * Hh;
    float* __restrict__       houtD  = d_h[wb] + (l * 2 + dir) * Bq * Hh;
    float* __restrict__       cstD   = d_c     + (l * 2 + dir) * Bq * Hh;
    const float* __restrict__ xbase  = (KIN == Ee) ? (d_x0 + t * Bq * Ee)
                                                   : (d_h[wb] + (l - 1) * 2 * Bq * Hh);
    const float* __restrict__ WihD   = (KIN == Ee) ? (d_Wih0 + dir * G4 * Ee)
                                                   : (d_WihL + ((l - 1) * 2 + dir) * G4 * 1024);
    const float* __restrict__ WhhD   = (KIN == Ee) ? (d_Whh0 + dir * G4 * Hh)
                                                   : (d_WhhL + ((l - 1) * 2 + dir) * G4 * Hh);

    auto load_stage = [&](int it, int buf) {
        const int k0 = it * 16;
        #pragma unroll
        for (int q = 0; q < 2; ++q) {
            int ch  = tid + q * 256;          // 0..511
            int row = ch >> 2, cc4 = (ch & 3) * 4;
            int kk  = k0 + cc4;
            // A tile: 128 batch rows x 16
            const float* srcA;
            int abg = b0 + row;
            if (kk < KIN) {
                if (KIN == Ee) srcA = xbase + abg * Ee + kk;
                else           srcA = xbase + ((kk >> 9) * Bq + abg) * Hh + (kk & 511);
            } else {
                srcA = hprevD + abg * Hh + (kk - KIN);
            }
            cp16(&sA[buf * 2560 + row * 20 + cc4], srcA);
            // B tile: 128 gate-cols x 16 (col n -> W row (n/32)*512 + j0 + n%32)
            int wrow = (row >> 5) * Hh + j0 + (row & 31);
            const float* srcB = (kk < KIN) ? (WihD + wrow * KIN + kk)
                                           : (WhhD + wrow * Hh + (kk - KIN));
            cp16(&sB[buf * 2560 + row * 20 + cc4], srcB);
        }
        cp_commit();
    };

    const int lane = tid & 31, wid = tid >> 5;
    const int wm = wid & 3, wn = wid >> 2;     // 4x2 warp grid, 32x64 warp tile
    const int g = lane >> 2, tg = lane & 3;

    float acc[2][8][4];
    #pragma unroll
    for (int i = 0; i < 2; i++)
        #pragma unroll
        for (int j = 0; j < 8; j++)
            #pragma unroll
            for (int k = 0; k < 4; k++) acc[i][j][k] = 0.f;

    load_stage(0, 0);
    for (int it = 0; it < NIT; ++it) {
        if (it + 1 < NIT) { load_stage(it + 1, (it + 1) & 1); cp_wait<1>(); }
        else              { cp_wait<0>(); }
        __syncthreads();
        const float* A  = sA + (it & 1) * 2560;
        const float* Bs = sB + (it & 1) * 2560;
        #pragma unroll
        for (int kc = 0; kc < 16; kc += 8) {
            uint32_t a[2][4];
            #pragma unroll
            for (int mi = 0; mi < 2; ++mi) {
                int r = wm * 32 + mi * 16 + g;
                a[mi][0] = __float_as_uint(A[r * 20 + kc + tg]);
                a[mi][1] = __float_as_uint(A[(r + 8) * 20 + kc + tg]);
                a[mi][2] = __float_as_uint(A[r * 20 + kc + tg + 4]);
                a[mi][3] = __float_as_uint(A[(r + 8) * 20 + kc + tg + 4]);
            }
            #pragma unroll
            for (int ni = 0; ni < 8; ++ni) {
                int n = wn * 64 + ni * 8 + g;
                uint32_t b0r = __float_as_uint(Bs[n * 20 + kc + tg]);
                uint32_t b1r = __float_as_uint(Bs[n * 20 + kc + tg + 4]);
                mma_tf32(acc[0][ni], a[0][0], a[0][1], a[0][2], a[0][3], b0r, b1r);
                mma_tf32(acc[1][ni], a[1][0], a[1][1], a[1][2], a[1][3], b0r, b1r);
            }
        }
        __syncthreads();
    }

    // ---- epilogue: two 64-row passes through smem (gt[64][133] = 8512 floats) ----
    float* gt = smem;
    const int jj = tid & 31;
    const int j  = j0 + jj;
    const float* biasD = d_bias + (l * 2 + dir) * G4;
    const float bi = biasD[0 * Hh + j];
    const float bf = biasD[1 * Hh + j];
    const float bg = biasD[2 * Hh + j];
    const float bo = biasD[3 * Hh + j];

    #pragma unroll
    for (int pass = 0; pass < 2; ++pass) {
        __syncthreads();
        if ((wm >> 1) == pass) {
            #pragma unroll
            for (int mi = 0; mi < 2; ++mi)
                #pragma unroll
                for (int ni = 0; ni < 8; ++ni) {
                    int r  = (wm & 1) * 32 + mi * 16 + g;
                    int cc = wn * 64 + ni * 8 + 2 * tg;
                    gt[r * 133 + cc]           = acc[mi][ni][0];
                    gt[r * 133 + cc + 1]       = acc[mi][ni][1];
                    gt[(r + 8) * 133 + cc]     = acc[mi][ni][2];
                    gt[(r + 8) * 133 + cc + 1] = acc[mi][ni][3];
                }
        }
        __syncthreads();
        const int rbase = tid >> 5;
        #pragma unroll
        for (int q = 0; q < 8; ++q) {
            int row = rbase + q * 8;            // 0..63
            int b = b0 + pass * 64 + row;
            float gi = gt[row * 133 + jj]      + bi;
            float gf = gt[row * 133 + 32 + jj] + bf;
            float gg = gt[row * 133 + 64 + jj] + bg;
            float go = gt[row * 133 + 96 + jj] + bo;
            float i_ = sigf(gi), f_ = sigf(gf), g_ = tanhf(gg), o_ = sigf(go);
            int idx = b * Hh + j;
            float cn = fmaf(f_, cstD[idx], i_ * g_);
            cstD[idx]  = cn;
            houtD[idx] = tf32r(o_ * tanhf(cn));   // h feeds tf32 GEMMs: pre-round (rna)
        }
    }
}

// ---------------- wavefront kernel: all independent (t,l) cells of one anti-diagonal ----------------
// grid = (2 mtiles, 16 jtiles, ncells*2); blockIdx.z = (cell_idx << 1) | dir
__global__ __launch_bounds__(256, 2) void lstm_wave(int w, int lmin) {
    __shared__ __align__(16) float smem[10240];
    const int cell = blockIdx.z >> 1;
    const int dir  = blockIdx.z & 1;
    const int l    = lmin + cell;
    const int t    = w - l;
    if (t < 0 || t >= Tn) return;
    if (l == 0) lstm_cell<Ee>(t, 0, dir, smem);
    else        lstm_cell<1024>(t, l, dir, smem);
}

// ---------------- final FC + softmax ----------------
__global__ __launch_bounds__(256) void fc_softmax(const float* __restrict__ fcw,
                                                  const float* __restrict__ fcb,
                                                  float* __restrict__ out) {
    const int b = blockIdx.x;
    const int tid = threadIdx.x, lane = tid & 31, w = tid >> 5;
    __shared__ float sv[64];
    const float* __restrict__ hf = d_h[(Tn - 1) % 3];   // t=127 wrote ring slot 1
    float acc[8] = {0, 0, 0, 0, 0, 0, 0, 0};
    for (int k = lane; k < 8192; k += 32) {
        int s = k >> 10, r = k & 1023;
        float hv = (r & 512) ? d_c[(s * Bq + b) * Hh + (r & 511)]
                             : hf[(s * Bq + b) * Hh + (r & 511)];
        #pragma unroll
        for (int q = 0; q < 8; ++q)
            acc[q] = fmaf(hv, fcw[(w * 8 + q) * 8192 + k], acc[q]);
    }
    #pragma unroll
    for (int q = 0; q < 8; ++q) {
        float v = acc[q];
        #pragma unroll
        for (int off = 16; off; off >>= 1) v += __shfl_xor_sync(0xffffffffu, v, off);
        if (lane == 0) sv[w * 8 + q] = v + fcb[w * 8 + q];
    }
    __syncthreads();
    if (tid < 32) {
        float v0 = sv[tid], v1 = sv[tid + 32];
        float m = fmaxf(v0, v1);
        #pragma unroll
        for (int off = 16; off; off >>= 1) m = fmaxf(m, __shfl_xor_sync(0xffffffffu, m, off));
        float e0 = expf(v0 - m), e1 = expf(v1 - m);
        float s = e0 + e1;
        #pragma unroll
        for (int off = 16; off; off >>= 1) s += __shfl_xor_sync(0xffffffffu, s, off);
        float inv = 1.0f / s;
        out[b * 64 + tid]      = e0 * inv;
        out[b * 64 + 32 + tid] = e1 * inv;
    }
}

// ---------------- launch ----------------
extern "C" void kernel_launch(void* const* d_in, const int* in_sizes, int n_in,
                              void* d_out, int out_size) {
    const int*   tokens = (const int*)  d_in[0];
    const float* embed  = (const float*)d_in[1];
    const float* Wih0   = (const float*)d_in[2];
    const float* Whh0   = (const float*)d_in[3];
    const float* bih0   = (const float*)d_in[4];
    const float* bhh0   = (const float*)d_in[5];
    const float* Wih    = (const float*)d_in[6];
    const float* Whh    = (const float*)d_in[7];
    const float* bih    = (const float*)d_in[8];
    const float* bhh    = (const float*)d_in[9];
    const float* fcw    = (const float*)d_in[10];
    const float* fcb    = (const float*)d_in[11];
    float*       out    = (float*)d_out;

    init_kernel<<<512, 256>>>(tokens, embed, Wih0, Whh0, bih0, bhh0, Wih, Whh, bih, bhh);

    // wavefront schedule: cells (t, l) with t + l == w are independent
    for (int w = 0; w <= (Tn - 1) + (Ln - 1); ++w) {
        int lmin = max(0, w - (Tn - 1));
        int lmax = min(Ln - 1, w);
        int ncells = lmax - lmin + 1;
        dim3 grid(2, 16, ncells * 2);
        lstm_wave<<<grid, 256>>>(w, lmin);
    }
    fc_softmax<<<Bq, 256>>>(fcw, fcb, out);
}

// round 5
// speedup vs baseline: 1.0940x; 1.0940x over previous
#include <cuda_runtime.h>
#include <cstdint>

// ---------------- problem constants ----------------
constexpr int Tn   = 128;   // seq len
constexpr int Bq   = 256;   // batch
constexpr int Hh   = 512;   // hidden
constexpr int Ee   = 16;    // embed
constexpr int Ln   = 4;     // layers
constexpr int G4   = 2048;  // 4H

// ---------------- device scratch (static; no allocation) ----------------
__device__ float d_Wih0[2 * G4 * Ee];           // tf32-rounded copies
__device__ float d_Whh0[2 * G4 * Hh];
__device__ float d_WihL[3 * 2 * G4 * 1024];
__device__ float d_WhhL[3 * 2 * G4 * Hh];
__device__ float d_bias[Ln * 2 * G4];           // bih + bhh
__device__ float d_x0[Tn * Bq * Ee];            // rounded embed[tokens]
__device__ float d_h[3][Ln * 2 * Bq * Hh];      // 3-deep ring of h state (wavefront-safe)
__device__ float d_c[Ln * 2 * Bq * Hh];         // c state (in-place)

// ---------------- helpers ----------------
__device__ __forceinline__ float tf32r(float x) {
    uint32_t u;
    asm("cvt.rna.tf32.f32 %0, %1;" : "=r"(u) : "f"(x));
    return __uint_as_float(u);
}

__device__ __forceinline__ void cp16(float* dst, const float* src) {
    unsigned s = (unsigned)__cvta_generic_to_shared(dst);
    asm volatile("cp.async.cg.shared.global [%0], [%1], 16;\n" :: "r"(s), "l"(src));
}
__device__ __forceinline__ void cp_commit() { asm volatile("cp.async.commit_group;\n"); }
template <int N>
__device__ __forceinline__ void cp_wait() { asm volatile("cp.async.wait_group %0;\n" :: "n"(N)); }

__device__ __forceinline__ void mma_tf32(float* c,
                                         uint32_t a0, uint32_t a1, uint32_t a2, uint32_t a3,
                                         uint32_t b0, uint32_t b1) {
    asm volatile(
        "mma.sync.aligned.m16n8k8.row.col.f32.tf32.tf32.f32 "
        "{%0,%1,%2,%3},{%4,%5,%6,%7},{%8,%9},{%0,%1,%2,%3};\n"
        : "+f"(c[0]), "+f"(c[1]), "+f"(c[2]), "+f"(c[3])
        : "r"(a0), "r"(a1), "r"(a2), "r"(a3), "r"(b0), "r"(b1));
}

__device__ __forceinline__ float sigf(float x) { return 1.0f / (1.0f + __expf(-x)); }

// ---------------- init ----------------
__global__ void init_kernel(const int* __restrict__ tokens, const float* __restrict__ embed,
                            const float* __restrict__ Wih0, const float* __restrict__ Whh0,
                            const float* __restrict__ bih0, const float* __restrict__ bhh0,
                            const float* __restrict__ Wih,  const float* __restrict__ Whh,
                            const float* __restrict__ bih,  const float* __restrict__ bhh) {
    const int idx0   = blockIdx.x * blockDim.x + threadIdx.x;
    const int stride = gridDim.x * blockDim.x;

    for (int i = idx0; i < 2 * G4 * Ee; i += stride)       d_Wih0[i] = tf32r(Wih0[i]);
    for (int i = idx0; i < 2 * G4 * Hh; i += stride)       d_Whh0[i] = tf32r(Whh0[i]);
    for (int i = idx0; i < 3 * 2 * G4 * 1024; i += stride) d_WihL[i] = tf32r(Wih[i]);
    for (int i = idx0; i < 3 * 2 * G4 * Hh; i += stride)   d_WhhL[i] = tf32r(Whh[i]);

    for (int i = idx0; i < Ln * 2 * G4; i += stride) {
        int l = i / (2 * G4), r = i % (2 * G4);
        d_bias[i] = (l == 0) ? (bih0[r] + bhh0[r])
                             : (bih[(l - 1) * 2 * G4 + r] + bhh[(l - 1) * 2 * G4 + r]);
    }
    for (int i = idx0; i < Tn * Bq * Ee; i += stride) {
        int t = i / (Bq * Ee);
        int rem = i % (Bq * Ee);
        int b = rem / Ee, e = rem % Ee;
        d_x0[i] = tf32r(embed[tokens[t * Bq + b] * Ee + e]);
    }
    for (int i = idx0; i < Ln * 2 * Bq * Hh; i += stride) {
        d_h[0][i] = 0.f;
        d_h[1][i] = 0.f;
        d_h[2][i] = 0.f;   // t=0 reads hprev from ring slot 2 -> must be zero
        d_c[i]    = 0.f;
    }
}

// ---------------- one LSTM cell (t, l, dir): 64 batch x 16 hidden units per block ----------------
// C tile [64, 64]: 64 batch rows x (4 gates x 16 units). 4 warps, 2x2 grid of 32x32 tiles.
// 3-stage cp.async pipeline, ONE __syncthreads per K-iter.
// Ring-buffer contract: cell (t,l) writes h into d_h[t%3]; reads hprev from d_h[(t+2)%3];
// reads x (l>0) from d_h[t%3] slot l-1 (written by (t,l-1) in an earlier wavefront).
template <int KIN>
__device__ __forceinline__ void lstm_cell(int t, int l, int dir, float* smem) {
    constexpr int NIT = (KIN + Hh) / 16;
    // stage s: sA = smem + s*2560, 64x20; sB = smem + s*2560 + 1280, 64x20
    const int tid = threadIdx.x;
    const int mt  = blockIdx.x;   // 0..3
    const int jt  = blockIdx.y;   // 0..31
    const int b0  = mt * 64, j0 = jt * 16;

    const int rb = (t + 2) % 3, wb = t % 3;
    const float* __restrict__ hprevD = d_h[rb] + (l * 2 + dir) * Bq * Hh;
    float* __restrict__       houtD  = d_h[wb] + (l * 2 + dir) * Bq * Hh;
    float* __restrict__       cstD   = d_c     + (l * 2 + dir) * Bq * Hh;
    const float* __restrict__ xbase  = (KIN == Ee) ? (d_x0 + t * Bq * Ee)
                                                   : (d_h[wb] + (l - 1) * 2 * Bq * Hh);
    const float* __restrict__ WihD   = (KIN == Ee) ? (d_Wih0 + dir * G4 * Ee)
                                                   : (d_WihL + ((l - 1) * 2 + dir) * G4 * 1024);
    const float* __restrict__ WhhD   = (KIN == Ee) ? (d_Whh0 + dir * G4 * Hh)
                                                   : (d_WhhL + ((l - 1) * 2 + dir) * G4 * Hh);

    const int lrow = tid >> 2, lc4 = (tid & 3) * 4;   // 32 rows x 16 k per 128 threads

    auto load_stage = [&](int it, int buf) {
        const int k0 = it * 16;
        float* sA = smem + buf * 2560;
        float* sB = sA + 1280;
        #pragma unroll
        for (int q = 0; q < 2; ++q) {
            int row = lrow + q * 32;          // 0..63
            int kk  = k0 + lc4;
            // A tile: 64 batch rows x 16
            const float* srcA;
            int abg = b0 + row;
            if (kk < KIN) {
                if (KIN == Ee) srcA = xbase + abg * Ee + kk;
                else           srcA = xbase + ((kk >> 9) * Bq + abg) * Hh + (kk & 511);
            } else {
                srcA = hprevD + abg * Hh + (kk - KIN);
            }
            cp16(&sA[row * 20 + lc4], srcA);
            // B tile: 64 gate-cols x 16 (col n -> W row (n/16)*512 + j0 + n%16)
            int wrow = (row >> 4) * Hh + j0 + (row & 15);
            const float* srcB = (kk < KIN) ? (WihD + wrow * KIN + kk)
                                           : (WhhD + wrow * Hh + (kk - KIN));
            cp16(&sB[row * 20 + lc4], srcB);
        }
        cp_commit();
    };

    const int lane = tid & 31, wid = tid >> 5;
    const int wm = wid & 1, wn = wid >> 1;     // 2x2 warp grid, 32x32 warp tile
    const int g = lane >> 2, tg = lane & 3;

    float acc[2][4][4];
    #pragma unroll
    for (int i = 0; i < 2; i++)
        #pragma unroll
        for (int j = 0; j < 4; j++)
            #pragma unroll
            for (int k = 0; k < 4; k++) acc[i][j][k] = 0.f;

    load_stage(0, 0);
    if (NIT > 1) load_stage(1, 1);
    for (int it = 0; it < NIT; ++it) {
        if (it + 1 < NIT) cp_wait<1>();   // stage it complete (it+1 may fly)
        else              cp_wait<0>();
        __syncthreads();
        if (it + 2 < NIT) load_stage(it + 2, (it + 2) % 3);
        const float* A  = smem + (it % 3) * 2560;
        const float* Bs = A + 1280;
        #pragma unroll
        for (int kc = 0; kc < 16; kc += 8) {
            uint32_t a[2][4];
            #pragma unroll
            for (int mi = 0; mi < 2; ++mi) {
                int r = wm * 32 + mi * 16 + g;
                a[mi][0] = __float_as_uint(A[r * 20 + kc + tg]);
                a[mi][1] = __float_as_uint(A[(r + 8) * 20 + kc + tg]);
                a[mi][2] = __float_as_uint(A[r * 20 + kc + tg + 4]);
                a[mi][3] = __float_as_uint(A[(r + 8) * 20 + kc + tg + 4]);
            }
            #pragma unroll
            for (int ni = 0; ni < 4; ++ni) {
                int n = wn * 32 + ni * 8 + g;
                uint32_t b0r = __float_as_uint(Bs[n * 20 + kc + tg]);
                uint32_t b1r = __float_as_uint(Bs[n * 20 + kc + tg + 4]);
                mma_tf32(acc[0][ni], a[0][0], a[0][1], a[0][2], a[0][3], b0r, b1r);
                mma_tf32(acc[1][ni], a[1][0], a[1][1], a[1][2], a[1][3], b0r, b1r);
            }
        }
    }
    __syncthreads();   // all reads of stage buffers done before reuse as gt

    // ---- epilogue: restage gates to smem gt[64][80] (stride 80: conflict-free reads) ----
    float* gt = smem;
    #pragma unroll
    for (int mi = 0; mi < 2; ++mi)
        #pragma unroll
        for (int ni = 0; ni < 4; ++ni) {
            int r  = wm * 32 + mi * 16 + g;
            int cc = wn * 32 + ni * 8 + 2 * tg;
            gt[r * 80 + cc]           = acc[mi][ni][0];
            gt[r * 80 + cc + 1]       = acc[mi][ni][1];
            gt[(r + 8) * 80 + cc]     = acc[mi][ni][2];
            gt[(r + 8) * 80 + cc + 1] = acc[mi][ni][3];
        }
    __syncthreads();

    // elementwise LSTM cell update: 64 rows x 16 units, 8 cells/thread
    const int jj = tid & 15;           // unit within tile
    const int rbase = tid >> 4;        // 0..7
    const float* biasD = d_bias + (l * 2 + dir) * G4;
    const int j = j0 + jj;
    const float bi = biasD[0 * Hh + j];
    const float bf = biasD[1 * Hh + j];
    const float bg = biasD[2 * Hh + j];
    const float bo = biasD[3 * Hh + j];
    #pragma unroll
    for (int q = 0; q < 8; ++q) {
        int row = rbase + q * 8;       // 0..63
        int b = b0 + row;
        float gi = gt[row * 80 +  0 + jj] + bi;
        float gf = gt[row * 80 + 16 + jj] + bf;
        float gg = gt[row * 80 + 32 + jj] + bg;
        float go = gt[row * 80 + 48 + jj] + bo;
        float i_ = sigf(gi), f_ = sigf(gf), g_ = tanhf(gg), o_ = sigf(go);
        int idx = b * Hh + j;
        float cn = fmaf(f_, cstD[idx], i_ * g_);
        cstD[idx]  = cn;
        houtD[idx] = tf32r(o_ * tanhf(cn));   // h feeds tf32 GEMMs: pre-round (rna)
    }
}

// ---------------- wavefront kernel: all independent (t,l) cells of one anti-diagonal ----------------
// grid = (4 mtiles, 32 jtiles, ncells*2); blockIdx.z = (cell_idx << 1) | dir
__global__ __launch_bounds__(128, 7) void lstm_wave(int w, int lmin) {
    __shared__ __align__(16) float smem[7680];   // 3 stages x (64x20 A + 64x20 B) = 30 KB
    const int cell = blockIdx.z >> 1;
    const int dir  = blockIdx.z & 1;
    const int l    = lmin + cell;
    const int t    = w - l;
    if (t < 0 || t >= Tn) return;
    if (l == 0) lstm_cell<Ee>(t, 0, dir, smem);
    else        lstm_cell<1024>(t, l, dir, smem);
}

// ---------------- final FC + softmax ----------------
__global__ __launch_bounds__(256) void fc_softmax(const float* __restrict__ fcw,
                                                  const float* __restrict__ fcb,
                                                  float* __restrict__ out) {
    const int b = blockIdx.x;
    const int tid = threadIdx.x, lane = tid & 31, w = tid >> 5;
    __shared__ float sv[64];
    const float* __restrict__ hf = d_h[(Tn - 1) % 3];   // t=127 wrote ring slot 1
    float acc[8] = {0, 0, 0, 0, 0, 0, 0, 0};
    for (int k = lane; k < 8192; k += 32) {
        int s = k >> 10, r = k & 1023;
        float hv = (r & 512) ? d_c[(s * Bq + b) * Hh + (r & 511)]
                             : hf[(s * Bq + b) * Hh + (r & 511)];
        #pragma unroll
        for (int q = 0; q < 8; ++q)
            acc[q] = fmaf(hv, fcw[(w * 8 + q) * 8192 + k], acc[q]);
    }
    #pragma unroll
    for (int q = 0; q < 8; ++q) {
        float v = acc[q];
        #pragma unroll
        for (int off = 16; off; off >>= 1) v += __shfl_xor_sync(0xffffffffu, v, off);
        if (lane == 0) sv[w * 8 + q] = v + fcb[w * 8 + q];
    }
    __syncthreads();
    if (tid < 32) {
        float v0 = sv[tid], v1 = sv[tid + 32];
        float m = fmaxf(v0, v1);
        #pragma unroll
        for (int off = 16; off; off >>= 1) m = fmaxf(m, __shfl_xor_sync(0xffffffffu, m, off));
        float e0 = expf(v0 - m), e1 = expf(v1 - m);
        float s = e0 + e1;
        #pragma unroll
        for (int off = 16; off; off >>= 1) s += __shfl_xor_sync(0xffffffffu, s, off);
        float inv = 1.0f / s;
        out[b * 64 + tid]      = e0 * inv;
        out[b * 64 + 32 + tid] = e1 * inv;
    }
}

// ---------------- launch ----------------
extern "C" void kernel_launch(void* const* d_in, const int* in_sizes, int n_in,
                              void* d_out, int out_size) {
    const int*   tokens = (const int*)  d_in[0];
    const float* embed  = (const float*)d_in[1];
    const float* Wih0   = (const float*)d_in[2];
    const float* Whh0   = (const float*)d_in[3];
    const float* bih0   = (const float*)d_in[4];
    const float* bhh0   = (const float*)d_in[5];
    const float* Wih    = (const float*)d_in[6];
    const float* Whh    = (const float*)d_in[7];
    const float* bih    = (const float*)d_in[8];
    const float* bhh    = (const float*)d_in[9];
    const float* fcw    = (const float*)d_in[10];
    const float* fcb    = (const float*)d_in[11];
    float*       out    = (float*)d_out;

    init_kernel<<<512, 256>>>(tokens, embed, Wih0, Whh0, bih0, bhh0, Wih, Whh, bih, bhh);

    // wavefront schedule: cells (t, l) with t + l == w are independent
    for (int w = 0; w <= (Tn - 1) + (Ln - 1); ++w) {
        int lmin = max(0, w - (Tn - 1));
        int lmax = min(Ln - 1, w);
        int ncells = lmax - lmin + 1;
        dim3 grid(4, 32, ncells * 2);
        lstm_wave<<<grid, 128>>>(w, lmin);
    }
    fc_softmax<<<Bq, 256>>>(fcw, fcb, out);
}